// round 9
// baseline (speedup 1.0000x reference)
#include <cuda_runtime.h>
#include <cuda_fp16.h>
#include <math_constants.h>
#include <cstdint>

// ============================================================================
// ContrastiveLoss: S = txt @ img^T once via single-pass fp16 mma.sync.
// Row-LSE (t2i) + Col-LSE (i2t) fused into the GEMM epilogue from register
// accumulators; CTA-level partial merge in smem; S never touches memory.
// R9: kill the 128-reg cap (R7/R8 spilled accumulators). 1 CTA/SM,
// launch_bounds(256,1); warp tile 64x64 (128 accum regs, no spill at 255);
// CTA tile 128x256; MMA:LDSM ratio doubled. R8's proven 4-stage pipeline.
// ============================================================================

#define B_DIM 4096
#define D_DIM 256
#define MARGIN 0.2f
#define INV_L  100.0f
#define SKIP   0.9f
#define SWZ(x) ((x) ^ (((x) >> 3) & 0x70))

__device__ __align__(16) __half g_txt_h[B_DIM * D_DIM];
__device__ __align__(16) __half g_img_h[B_DIM * D_DIM];
__device__ float2 g_rowp[B_DIM * 16];     // (row, ntile 0..15)
__device__ float2 g_colp[B_DIM * 32];     // (col, mtile 0..31)
__device__ float  g_pos[B_DIM];
__device__ float  g_loss[2 * B_DIM];

// ---- PTX helpers (sm_80-portable only) ----
__device__ __forceinline__ uint32_t smem_u32(const void* p) {
    uint32_t a;
    asm("{ .reg .u64 t; cvta.to.shared.u64 t, %1; cvt.u32.u64 %0, t; }" : "=r"(a) : "l"(p));
    return a;
}
__device__ __forceinline__ void cpa16(uint32_t dst, const void* src) {
    asm volatile("cp.async.cg.shared.global [%0], [%1], 16;" :: "r"(dst), "l"(src));
}
#define CP_COMMIT() asm volatile("cp.async.commit_group;" ::: "memory")
#define CP_WAIT(n)  asm volatile("cp.async.wait_group %0;" :: "n"(n) : "memory")

__device__ __forceinline__ void ldm4(uint32_t* r, uint32_t addr) {
    asm volatile("ldmatrix.sync.aligned.m8n8.x4.shared.b16 {%0,%1,%2,%3}, [%4];"
                 : "=r"(r[0]), "=r"(r[1]), "=r"(r[2]), "=r"(r[3]) : "r"(addr));
}
__device__ __forceinline__ void mma_f16(float* c, const uint32_t* a, uint32_t b0, uint32_t b1) {
    asm volatile("mma.sync.aligned.m16n8k16.row.col.f32.f16.f16.f32 "
                 "{%0,%1,%2,%3}, {%4,%5,%6,%7}, {%8,%9}, {%0,%1,%2,%3};"
                 : "+f"(c[0]), "+f"(c[1]), "+f"(c[2]), "+f"(c[3])
                 : "r"(a[0]), "r"(a[1]), "r"(a[2]), "r"(a[3]), "r"(b0), "r"(b1));
}

__device__ __forceinline__ void lse_merge(float& m, float& s, float m2, float s2) {
    if (m2 > m) { s = s * __expf((m - m2) * INV_L) + s2; m = m2; }
    else if (s2 > 0.f) s += s2 * __expf((m2 - m) * INV_L);
}
__device__ __forceinline__ void lse_accum(float& m, float& s, float v) {
    if (v > m) { s = s * __expf((m - v) * INV_L) + 1.f; m = v; }
    else if (v > m - SKIP) s += __expf((v - m) * INV_L);
}
__device__ __forceinline__ float finish_loss(float m, float s, float pos) {
    float M = fmaxf(m, pos);
    float tot = __expf((pos - M) * INV_L) + s * __expf((m - M) * INV_L);
    return (M - pos) * INV_L + logf(tot);
}

// ---------------------------------------------------------------------------
// Convert fp32 -> fp16 plane, row-major. 1 thread = 8 elements.
// ---------------------------------------------------------------------------
__global__ void __launch_bounds__(256) convert_h(const float* __restrict__ img,
                                                 const float* __restrict__ txt) {
    const float* src = (blockIdx.y == 0) ? img : txt;
    char* dst = (char*)((blockIdx.y == 0) ? g_img_h : g_txt_h);
    int idx = blockIdx.x * 256 + threadIdx.x;
    size_t e0 = (size_t)idx * 8;
    float4 a = *(const float4*)(src + e0);
    float4 b = *(const float4*)(src + e0 + 4);
    float x[8] = {a.x, a.y, a.z, a.w, b.x, b.y, b.z, b.w};
    union { __half h[8]; uint4 u; } H;
#pragma unroll
    for (int i = 0; i < 8; i++) H.h[i] = __float2half_rn(x[i]);
    *(uint4*)(dst + e0 * 2) = H.u;
}

// ---------------------------------------------------------------------------
// GEMM + fused row/col LSE. CTA tile 128(M) x 256(N), 8 warps = 2(M) x 4(N),
// warp tile 64x64 (128 accum regs). K: 8 chunks of 32; 4-stage pipeline.
// Stage = A(8KB) + B(16KB) = 24KB; 4 stages + pad = 97KB -> 1 CTA/SM.
// ---------------------------------------------------------------------------
#define STAGE 24576
#define A_OFF 0
#define B_OFF 8192
#define SMEM_TOTAL (4 * STAGE + 1024)

// A chunk: 128 rows x 64B = 512 x 16B; B chunk: 256 rows x 64B = 1024 x 16B
__device__ __forceinline__ void load_stage(uint32_t buf, const char* At, const char* Bi,
                                           int m0, int n0, int s, int tid) {
#pragma unroll
    for (int it = 0; it < 2; it++) {
        int idx = it * 256 + tid;
        int r = idx >> 2, u = idx & 3;
        uint32_t off = (uint32_t)(r * 64 + u * 16);
        cpa16(buf + A_OFF + SWZ(off), At + (size_t)(m0 + r) * 512 + s * 64 + u * 16);
    }
#pragma unroll
    for (int it = 0; it < 4; it++) {
        int idx = it * 256 + tid;
        int r = idx >> 2, u = idx & 3;
        uint32_t off = (uint32_t)(r * 64 + u * 16);
        cpa16(buf + B_OFF + SWZ(off), Bi + (size_t)(n0 + r) * 512 + s * 64 + u * 16);
    }
    CP_COMMIT();
}

__global__ void __launch_bounds__(256, 1) gemm_lse() {
    extern __shared__ char smem[];
    const uint32_t sb = (smem_u32(smem) + 1023) & ~1023u;

    const int tid = threadIdx.x, lane = tid & 31, wid = tid >> 5;
    const int warp_m = wid & 1, warp_n = wid >> 1;       // 2(M) x 4(N)
    const int ntile = blockIdx.x, mtile = blockIdx.y;
    const int m0 = mtile * 128, n0 = ntile * 256;

    const char* At = (const char*)g_txt_h;
    const char* Bi = (const char*)g_img_h;

    float c[4][8][4];                                    // [mi][q=p*2+h][frag]
#pragma unroll
    for (int i = 0; i < 4; i++)
#pragma unroll
        for (int j = 0; j < 8; j++)
#pragma unroll
            for (int k = 0; k < 4; k++) c[i][j][k] = 0.f;

    // ldmatrix lane coords for 64B-wide (K=32) smem rows
    const int a_row = warp_m * 64 + (lane & 15);
    const int a_kb  = (lane >> 4) << 4;                  // 0 / 16 B
    const int b_row = warp_n * 64 + (lane & 7) + ((lane >> 4) << 3);
    const int b_kb  = ((lane >> 3) & 1) << 4;

    // prologue: stages 0..2 (3 groups in flight)
#pragma unroll
    for (int s = 0; s < 3; s++)
        load_stage(sb + s * STAGE, At, Bi, m0, n0, s, tid);

    // wait counts: iter s completes stage s (the (s+1)th group):
    // committed before loop-commit = min(8, s+3); s<=5 -> 2, s=6 -> 1, s=7 -> 0
#pragma unroll
    for (int s = 0; s < 8; s++) {
        if (s <= 5) CP_WAIT(2);
        else if (s == 6) CP_WAIT(1);
        else CP_WAIT(0);
        __syncthreads();    // also protects buf (s+3)&3, consumed at iter s-1

        if (s + 3 < 8)
            load_stage(sb + ((s + 3) & 3) * STAGE, At, Bi, m0, n0, s + 3, tid);

        const uint32_t bb = sb + (s & 3) * STAGE;
#pragma unroll
        for (int ks = 0; ks < 2; ks++) {                 // two K=16 steps
            const int kb = ks * 32;
            uint32_t ah[4][4];
#pragma unroll
            for (int mi = 0; mi < 4; mi++)
                ldm4(ah[mi], bb + A_OFF + SWZ((uint32_t)((a_row + mi * 16) * 64 + kb + a_kb)));
            uint32_t bh[4][4];
#pragma unroll
            for (int p = 0; p < 4; p++)
                ldm4(bh[p], bb + B_OFF + SWZ((uint32_t)((b_row + p * 16) * 64 + kb + b_kb)));
#pragma unroll
            for (int mi = 0; mi < 4; mi++)
#pragma unroll
                for (int p = 0; p < 4; p++)
#pragma unroll
                    for (int h = 0; h < 2; h++)
                        mma_f16(c[mi][p * 2 + h], ah[mi], bh[p][h * 2], bh[p][h * 2 + 1]);
        }
    }
    __syncthreads();        // compute done; epilogue reuses stage smem

    // ---- epilogue: per-thread online LSE, then CTA-level partial merge ----
    const int gID = lane >> 2, tig = lane & 3;
    const int mb = m0 + warp_m * 64;
    const int nb = n0 + warp_n * 64;

    float2* rowp = (float2*)smem;              // [128][4]  (row_in_cta, warp_n)
    float2* colp = (float2*)(smem + 4096);     // [256][2]  (col_in_cta, warp_m)

    // rows (t2i): 8 rows/thread, 16 cols each; quad merge -> 64-col partial
#pragma unroll
    for (int mi = 0; mi < 4; mi++)
#pragma unroll
        for (int r = 0; r < 2; r++) {
            const int m = mb + mi * 16 + gID + 8 * r;
            float mm = -CUDART_INF_F, ss = 0.f;
#pragma unroll
            for (int q = 0; q < 8; q++)
#pragma unroll
                for (int j = 0; j < 2; j++) {
                    const int n = nb + q * 8 + tig * 2 + j;
                    float v = c[mi][q][r * 2 + j];
                    if (n == m) { g_pos[m] = v; continue; }
                    lse_accum(mm, ss, v + MARGIN);
                }
#pragma unroll
            for (int d = 1; d <= 2; d <<= 1) {
                float m2 = __shfl_xor_sync(0xffffffffu, mm, d);
                float s2 = __shfl_xor_sync(0xffffffffu, ss, d);
                lse_merge(mm, ss, m2, s2);
            }
            if (tig == 0)
                rowp[(warp_m * 64 + mi * 16 + gID + 8 * r) * 4 + warp_n] = make_float2(mm, ss);
        }

    // cols (i2t): 16 cols/thread, 8 rows each; gID merge -> 64-row partial
#pragma unroll
    for (int q = 0; q < 8; q++)
#pragma unroll
        for (int j = 0; j < 2; j++) {
            const int n = nb + q * 8 + tig * 2 + j;
            float mm = -CUDART_INF_F, ss = 0.f;
#pragma unroll
            for (int mi = 0; mi < 4; mi++)
#pragma unroll
                for (int r = 0; r < 2; r++) {
                    const int m = mb + mi * 16 + gID + 8 * r;
                    if (m == n) continue;
                    lse_accum(mm, ss, c[mi][q][r * 2 + j] + MARGIN);
                }
#pragma unroll
            for (int d = 4; d <= 16; d <<= 1) {
                float m2 = __shfl_xor_sync(0xffffffffu, mm, d);
                float s2 = __shfl_xor_sync(0xffffffffu, ss, d);
                lse_merge(mm, ss, m2, s2);
            }
            if (gID == 0)
                colp[(warp_n * 64 + q * 8 + tig * 2 + j) * 2 + warp_m] = make_float2(mm, ss);
        }

    __syncthreads();
    if (tid < 128) {        // rows: merge 4 warp_n partials
        float2 a0 = rowp[tid * 4], a1 = rowp[tid * 4 + 1];
        float2 a2 = rowp[tid * 4 + 2], a3 = rowp[tid * 4 + 3];
        float m = a0.x, s = a0.y;
        lse_merge(m, s, a1.x, a1.y);
        lse_merge(m, s, a2.x, a2.y);
        lse_merge(m, s, a3.x, a3.y);
        g_rowp[(size_t)(m0 + tid) * 16 + ntile] = make_float2(m, s);
    }
    {                       // cols: all 256 threads merge 2 warp_m partials
        float2 q0 = colp[tid * 2], q1 = colp[tid * 2 + 1];
        float cm = q0.x, cs = q0.y;
        lse_merge(cm, cs, q1.x, q1.y);
        g_colp[(size_t)(n0 + tid) * 32 + mtile] = make_float2(cm, cs);
    }
}

// ---------------------------------------------------------------------------
// Merge partials (16/row, 32/col) -> per-row losses. One warp per id.
// ---------------------------------------------------------------------------
__global__ void __launch_bounds__(256) merge_rowscols() {
    const int wid = threadIdx.x >> 5, lane = threadIdx.x & 31;
    const int id = blockIdx.x * 8 + wid;            // 0..8191
    float m = -CUDART_INF_F, s = 0.f;
    if (id < B_DIM) {
        if (lane < 16) {
            float2 p = g_rowp[(size_t)id * 16 + lane];
            m = p.x; s = p.y;
        }
    } else {
        float2 p = g_colp[(size_t)(id - B_DIM) * 32 + lane];
        m = p.x; s = p.y;
    }
#pragma unroll
    for (int d = 16; d; d >>= 1) {
        float m2 = __shfl_xor_sync(0xffffffffu, m, d);
        float s2 = __shfl_xor_sync(0xffffffffu, s, d);
        lse_merge(m, s, m2, s2);
    }
    if (lane == 0) g_loss[id] = finish_loss(m, s, g_pos[id & (B_DIM - 1)]);
}

__global__ void __launch_bounds__(512) final_reduce(float* __restrict__ out) {
    __shared__ double sh[512];
    const float4* L = (const float4*)g_loss;
    float4 v = L[threadIdx.x];
    float4 w = L[threadIdx.x + 512];
    float4 x = L[threadIdx.x + 1024];
    float4 y = L[threadIdx.x + 1536];
    sh[threadIdx.x] = (double)v.x + v.y + v.z + v.w + (double)w.x + w.y + w.z + w.w
                    + (double)x.x + x.y + x.z + x.w + (double)y.x + y.y + y.z + y.w;
    __syncthreads();
    for (int off = 256; off; off >>= 1) {
        if (threadIdx.x < off) sh[threadIdx.x] += sh[threadIdx.x + off];
        __syncthreads();
    }
    if (threadIdx.x == 0) out[0] = (float)(sh[0] / (2.0 * B_DIM));
}

// ---------------------------------------------------------------------------
extern "C" void kernel_launch(void* const* d_in, const int* in_sizes, int n_in,
                              void* d_out, int out_size) {
    const float* img = (const float*)d_in[0];
    const float* txt = (const float*)d_in[1];

    cudaFuncSetAttribute(gemm_lse, cudaFuncAttributeMaxDynamicSharedMemorySize, SMEM_TOTAL);

    convert_h<<<dim3(512, 2), 256>>>(img, txt);
    gemm_lse<<<dim3(16, 32), 256, SMEM_TOTAL>>>();
    merge_rowscols<<<1024, 256>>>();
    final_reduce<<<1, 512>>>((float*)d_out);
}

// round 11
// speedup vs baseline: 3.2605x; 3.2605x over previous
#include <cuda_runtime.h>
#include <cuda_fp16.h>
#include <math_constants.h>
#include <cstdint>

// ============================================================================
// ContrastiveLoss: S = txt @ img^T once via single-pass fp16 mma.sync.
// Row-LSE (t2i) + Col-LSE (i2t) fused into the GEMM epilogue.
// R11 (= R10 resubmission; R10 hit a broker-container flake, not a kernel
// failure). Mainloop identical to R8 (best passing: 110.6us). Epilogue is
// BRANCH-FREE: pass 1 = fmaxf reduction (diag -> -INF via select), pass 2 =
// unconditional sum of __expf((v-M)*100) (fp32 underflow implements the
// skip threshold exactly), shfl max/add merges. Kills the BSSY/BSYNC
// divergence cost of the online-LSE form.
// ============================================================================

#define B_DIM 4096
#define D_DIM 256
#define MARGIN 0.2f
#define INV_L  100.0f
#define SWZ(x) ((x) ^ (((x) >> 3) & 0x70))

__device__ __align__(16) __half g_txt_h[B_DIM * D_DIM];
__device__ __align__(16) __half g_img_h[B_DIM * D_DIM];
__device__ float2 g_rowp[B_DIM * 32];     // (row, ntile)
__device__ float2 g_colp[B_DIM * 32];     // (col, mtile)
__device__ float  g_pos[B_DIM];
__device__ float  g_loss[2 * B_DIM];

// ---- PTX helpers (sm_80-portable only) ----
__device__ __forceinline__ uint32_t smem_u32(const void* p) {
    uint32_t a;
    asm("{ .reg .u64 t; cvta.to.shared.u64 t, %1; cvt.u32.u64 %0, t; }" : "=r"(a) : "l"(p));
    return a;
}
__device__ __forceinline__ void cpa16(uint32_t dst, const void* src) {
    asm volatile("cp.async.cg.shared.global [%0], [%1], 16;" :: "r"(dst), "l"(src));
}
#define CP_COMMIT() asm volatile("cp.async.commit_group;" ::: "memory")
#define CP_WAIT(n)  asm volatile("cp.async.wait_group %0;" :: "n"(n) : "memory")

__device__ __forceinline__ void ldm4(uint32_t* r, uint32_t addr) {
    asm volatile("ldmatrix.sync.aligned.m8n8.x4.shared.b16 {%0,%1,%2,%3}, [%4];"
                 : "=r"(r[0]), "=r"(r[1]), "=r"(r[2]), "=r"(r[3]) : "r"(addr));
}
__device__ __forceinline__ void mma_f16(float* c, const uint32_t* a, uint32_t b0, uint32_t b1) {
    asm volatile("mma.sync.aligned.m16n8k16.row.col.f32.f16.f16.f32 "
                 "{%0,%1,%2,%3}, {%4,%5,%6,%7}, {%8,%9}, {%0,%1,%2,%3};"
                 : "+f"(c[0]), "+f"(c[1]), "+f"(c[2]), "+f"(c[3])
                 : "r"(a[0]), "r"(a[1]), "r"(a[2]), "r"(a[3]), "r"(b0), "r"(b1));
}

__device__ __forceinline__ void lse_merge(float& m, float& s, float m2, float s2) {
    if (m2 > m) { s = s * __expf((m - m2) * INV_L) + s2; m = m2; }
    else if (s2 > 0.f) s += s2 * __expf((m2 - m) * INV_L);
}
__device__ __forceinline__ float finish_loss(float m, float s, float pos) {
    float M = fmaxf(m, pos);
    float tot = __expf((pos - M) * INV_L) + s * __expf((m - M) * INV_L);
    return (M - pos) * INV_L + logf(tot);
}

// ---------------------------------------------------------------------------
// Convert fp32 -> fp16 plane, row-major. 1 thread = 8 elements.
// ---------------------------------------------------------------------------
__global__ void __launch_bounds__(256) convert_h(const float* __restrict__ img,
                                                 const float* __restrict__ txt) {
    const float* src = (blockIdx.y == 0) ? img : txt;
    char* dst = (char*)((blockIdx.y == 0) ? g_img_h : g_txt_h);
    int idx = blockIdx.x * 256 + threadIdx.x;
    size_t e0 = (size_t)idx * 8;
    float4 a = *(const float4*)(src + e0);
    float4 b = *(const float4*)(src + e0 + 4);
    float x[8] = {a.x, a.y, a.z, a.w, b.x, b.y, b.z, b.w};
    union { __half h[8]; uint4 u; } H;
#pragma unroll
    for (int i = 0; i < 8; i++) H.h[i] = __float2half_rn(x[i]);
    *(uint4*)(dst + e0 * 2) = H.u;
}

// ---------------------------------------------------------------------------
// GEMM + fused row/col LSE. CTA tile 128x128, 8 warps = 4(M) x 2(N),
// warp tile 32x64. K: 8 chunks of 32; 4-stage cp.async circular pipeline.
// Stage = A(8KB) + B(8KB) = 16KB; 4 stages + pad = 66KB -> 2 CTAs/SM.
// ---------------------------------------------------------------------------
#define STAGE 16384
#define A_OFF 0
#define B_OFF 8192
#define SMEM_TOTAL (4 * STAGE + 1024)

__device__ __forceinline__ void load_mat(uint32_t dst, const char* src, int row0, int s, int tid) {
#pragma unroll
    for (int it = 0; it < 2; it++) {
        int idx = it * 256 + tid;
        int r = idx >> 2, u = idx & 3;
        uint32_t off = (uint32_t)(r * 64 + u * 16);
        cpa16(dst + SWZ(off), src + (size_t)(row0 + r) * 512 + s * 64 + u * 16);
    }
}

__global__ void __launch_bounds__(256, 2) gemm_lse() {
    extern __shared__ char smem[];
    const uint32_t sb = (smem_u32(smem) + 1023) & ~1023u;

    const int tid = threadIdx.x, lane = tid & 31, wid = tid >> 5;
    const int warp_m = wid & 3, warp_n = wid >> 2;
    const int ntile = blockIdx.x, mtile = blockIdx.y;
    const int m0 = mtile * 128, n0 = ntile * 128;

    const char* At = (const char*)g_txt_h;
    const char* Bi = (const char*)g_img_h;

    float c[2][8][4];
#pragma unroll
    for (int i = 0; i < 2; i++)
#pragma unroll
        for (int j = 0; j < 8; j++)
#pragma unroll
            for (int k = 0; k < 4; k++) c[i][j][k] = 0.f;

    const int a_row = warp_m * 32 + (lane & 15);
    const int a_kb  = (lane >> 4) << 4;
    const int b_row = warp_n * 64 + (lane & 7) + ((lane >> 4) << 3);
    const int b_kb  = ((lane >> 3) & 1) << 4;

    // prologue: stages 0..2 (3 groups in flight)
#pragma unroll
    for (int s = 0; s < 3; s++) {
        uint32_t bb = sb + s * STAGE;
        load_mat(bb + A_OFF, At, m0, s, tid);
        load_mat(bb + B_OFF, Bi, n0, s, tid);
        CP_COMMIT();
    }

#pragma unroll
    for (int s = 0; s < 8; s++) {
        if (s <= 5) CP_WAIT(2);
        else if (s == 6) CP_WAIT(1);
        else CP_WAIT(0);
        __syncthreads();

        if (s + 3 < 8) {
            uint32_t bb2 = sb + ((s + 3) & 3) * STAGE;
            load_mat(bb2 + A_OFF, At, m0, s + 3, tid);
            load_mat(bb2 + B_OFF, Bi, n0, s + 3, tid);
            CP_COMMIT();
        }

        const uint32_t bb = sb + (s & 3) * STAGE;
#pragma unroll
        for (int ks = 0; ks < 2; ks++) {
            const int kb = ks * 32;
            uint32_t ah[2][4];
#pragma unroll
            for (int mi = 0; mi < 2; mi++)
                ldm4(ah[mi], bb + A_OFF + SWZ((uint32_t)((a_row + mi * 16) * 64 + kb + a_kb)));
            uint32_t bh[4][4];
#pragma unroll
            for (int p = 0; p < 4; p++)
                ldm4(bh[p], bb + B_OFF + SWZ((uint32_t)((b_row + p * 16) * 64 + kb + b_kb)));
#pragma unroll
            for (int mi = 0; mi < 2; mi++)
#pragma unroll
                for (int p = 0; p < 4; p++)
#pragma unroll
                    for (int h = 0; h < 2; h++)
                        mma_f16(c[mi][p * 2 + h], ah[mi], bh[p][h * 2], bh[p][h * 2 + 1]);
        }
    }
    __syncthreads();

    // ---- epilogue: BRANCH-FREE two-pass LSE ----
    const int gID = lane >> 2, tig = lane & 3;
    const int mb = m0 + warp_m * 32;
    const int nb = n0 + warp_n * 64;

    float2* rowp = (float2*)smem;              // [128][2]
    float2* colp = (float2*)(smem + 2048);     // [128][4]

    // rows (t2i): 4 rows/thread x 16 cols; quad shfl max+sum
#pragma unroll
    for (int mi = 0; mi < 2; mi++)
#pragma unroll
        for (int r = 0; r < 2; r++) {
            const int m = mb + mi * 16 + gID + 8 * r;
            float mm = -CUDART_INF_F;
#pragma unroll
            for (int q = 0; q < 8; q++)
#pragma unroll
                for (int j = 0; j < 2; j++) {
                    const int n = nb + q * 8 + tig * 2 + j;
                    float raw = c[mi][q][r * 2 + j];
                    if (n == m) g_pos[m] = raw;                // predicated STG
                    float v = (n == m) ? -CUDART_INF_F : raw + MARGIN;
                    mm = fmaxf(mm, v);
                }
#pragma unroll
            for (int d = 1; d <= 2; d <<= 1)
                mm = fmaxf(mm, __shfl_xor_sync(0xffffffffu, mm, d));
            float ss = 0.f;
#pragma unroll
            for (int q = 0; q < 8; q++)
#pragma unroll
                for (int j = 0; j < 2; j++) {
                    const int n = nb + q * 8 + tig * 2 + j;
                    float v = (n == m) ? -CUDART_INF_F : c[mi][q][r * 2 + j] + MARGIN;
                    ss += __expf(v * INV_L - mm * INV_L);
                }
#pragma unroll
            for (int d = 1; d <= 2; d <<= 1)
                ss += __shfl_xor_sync(0xffffffffu, ss, d);
            if (tig == 0)
                rowp[(warp_m * 32 + mi * 16 + gID + 8 * r) * 2 + warp_n] = make_float2(mm, ss);
        }

    // cols (i2t): 16 cols/thread x 4 rows; gID-direction shfl max+sum
#pragma unroll
    for (int q = 0; q < 8; q++)
#pragma unroll
        for (int j = 0; j < 2; j++) {
            const int n = nb + q * 8 + tig * 2 + j;
            float mm = -CUDART_INF_F;
#pragma unroll
            for (int mi = 0; mi < 2; mi++)
#pragma unroll
                for (int r = 0; r < 2; r++) {
                    const int m = mb + mi * 16 + gID + 8 * r;
                    float v = (m == n) ? -CUDART_INF_F : c[mi][q][r * 2 + j] + MARGIN;
                    mm = fmaxf(mm, v);
                }
#pragma unroll
            for (int d = 4; d <= 16; d <<= 1)
                mm = fmaxf(mm, __shfl_xor_sync(0xffffffffu, mm, d));
            float ss = 0.f;
#pragma unroll
            for (int mi = 0; mi < 2; mi++)
#pragma unroll
                for (int r = 0; r < 2; r++) {
                    const int m = mb + mi * 16 + gID + 8 * r;
                    float v = (m == n) ? -CUDART_INF_F : c[mi][q][r * 2 + j] + MARGIN;
                    ss += __expf(v * INV_L - mm * INV_L);
                }
#pragma unroll
            for (int d = 4; d <= 16; d <<= 1)
                ss += __shfl_xor_sync(0xffffffffu, ss, d);
            if (gID == 0)
                colp[(warp_n * 64 + q * 8 + tig * 2 + j) * 4 + warp_m] = make_float2(mm, ss);
        }

    __syncthreads();
    if (tid < 128) {
        float2 a0 = rowp[tid * 2], a1 = rowp[tid * 2 + 1];
        float m = a0.x, s = a0.y;
        lse_merge(m, s, a1.x, a1.y);
        g_rowp[(size_t)(m0 + tid) * 32 + ntile] = make_float2(m, s);

        float2 q0 = colp[tid * 4], q1 = colp[tid * 4 + 1];
        float2 q2 = colp[tid * 4 + 2], q3 = colp[tid * 4 + 3];
        float cm = q0.x, cs = q0.y;
        lse_merge(cm, cs, q1.x, q1.y);
        lse_merge(cm, cs, q2.x, q2.y);
        lse_merge(cm, cs, q3.x, q3.y);
        g_colp[(size_t)(n0 + tid) * 32 + mtile] = make_float2(cm, cs);
    }
}

// ---------------------------------------------------------------------------
// Merge 32 partials per row / per col -> per-row losses. One warp per id.
// ---------------------------------------------------------------------------
__global__ void __launch_bounds__(256) merge_rowscols() {
    const int wid = threadIdx.x >> 5, lane = threadIdx.x & 31;
    const int id = blockIdx.x * 8 + wid;            // 0..8191
    float2 p = (id < B_DIM) ? g_rowp[(size_t)id * 32 + lane]
                            : g_colp[(size_t)(id - B_DIM) * 32 + lane];
    // branch-free warp merge: global max first, then rescaled sums
    float m = p.x, s = p.y;
    float gm = m;
#pragma unroll
    for (int d = 16; d; d >>= 1)
        gm = fmaxf(gm, __shfl_xor_sync(0xffffffffu, gm, d));
    s *= __expf((m - gm) * INV_L);
#pragma unroll
    for (int d = 16; d; d >>= 1)
        s += __shfl_xor_sync(0xffffffffu, s, d);
    if (lane == 0) g_loss[id] = finish_loss(gm, s, g_pos[id & (B_DIM - 1)]);
}

__global__ void __launch_bounds__(512) final_reduce(float* __restrict__ out) {
    __shared__ double sh[512];
    const float4* L = (const float4*)g_loss;
    float4 v = L[threadIdx.x];
    float4 w = L[threadIdx.x + 512];
    float4 x = L[threadIdx.x + 1024];
    float4 y = L[threadIdx.x + 1536];
    sh[threadIdx.x] = (double)v.x + v.y + v.z + v.w + (double)w.x + w.y + w.z + w.w
                    + (double)x.x + x.y + x.z + x.w + (double)y.x + y.y + y.z + y.w;
    __syncthreads();
    for (int off = 256; off; off >>= 1) {
        if (threadIdx.x < off) sh[threadIdx.x] += sh[threadIdx.x + off];
        __syncthreads();
    }
    if (threadIdx.x == 0) out[0] = (float)(sh[0] / (2.0 * B_DIM));
}

// ---------------------------------------------------------------------------
extern "C" void kernel_launch(void* const* d_in, const int* in_sizes, int n_in,
                              void* d_out, int out_size) {
    const float* img = (const float*)d_in[0];
    const float* txt = (const float*)d_in[1];

    cudaFuncSetAttribute(gemm_lse, cudaFuncAttributeMaxDynamicSharedMemorySize, SMEM_TOTAL);

    convert_h<<<dim3(512, 2), 256>>>(img, txt);
    gemm_lse<<<dim3(32, 32), 256, SMEM_TOTAL>>>();
    merge_rowscols<<<1024, 256>>>();
    final_reduce<<<1, 512>>>((float*)d_out);
}